// round 8
// baseline (speedup 1.0000x reference)
#include <cuda_runtime.h>
#include <cuda_fp16.h>
#include <math.h>
#include <cstdint>

#define BATCH 2048
#define SEQ   200
#define HDIM  512
#define MTOT  (BATCH * SEQ)   // 409600
#define NPLANES 4             // 4 o-tiles of 128 cols

// ---------------- static device scratch (no allocation) ----------------
__device__ float  g_l[BATCH * HDIM];          // Wr(last_memory)  [B,512]
__device__ float  g_spart[NPLANES][MTOT];     // partial scores
__device__ __half g_Wh[HDIM * HDIM];          // Ur_w fp16
__device__ __half g_Ah[(size_t)MTOT * HDIM];  // all_memory fp16 (419 MB)

// ======================= helpers =======================
__device__ __forceinline__ uint32_t smem_u32(const void* p) {
    uint32_t a;
    asm("{ .reg .u64 t; cvta.to.shared.u64 t, %1; cvt.u32.u64 %0, t; }"
        : "=r"(a) : "l"(p));
    return a;
}
#define SWZ(off) ((off) ^ (((off) >> 3) & 0x70))

#define LDSM_X4(r, a) \
    asm volatile("ldmatrix.sync.aligned.m8n8.x4.shared.b16 {%0,%1,%2,%3}, [%4];" \
        : "=r"((r)[0]), "=r"((r)[1]), "=r"((r)[2]), "=r"((r)[3]) : "r"(a))
#define MMA_F16(d, a, b) \
    asm volatile("mma.sync.aligned.m16n8k16.row.col.f32.f16.f16.f32 " \
        "{%0,%1,%2,%3},{%4,%5,%6,%7},{%8,%9},{%0,%1,%2,%3};" \
        : "+f"((d)[0]), "+f"((d)[1]), "+f"((d)[2]), "+f"((d)[3]) \
        : "r"((a)[0]), "r"((a)[1]), "r"((a)[2]), "r"((a)[3]), \
          "r"((b)[0]), "r"((b)[1]))
#define CPASYNC16(dst, src) \
    asm volatile("cp.async.cg.shared.global [%0], [%1], 16;" \
        :: "r"(dst), "l"(src) : "memory")
#define CPASYNC_COMMIT() asm volatile("cp.async.commit_group;" ::: "memory")
#define CPASYNC_WAITG(n) asm volatile("cp.async.wait_group %0;" :: "n"(n) : "memory")

__device__ __forceinline__ float fast_tanh(float x) {
    float e = __expf(2.0f * x);
    return 1.0f - __fdividef(2.0f, e + 1.0f);
}

// =============================================================================
// convert kernel (lightweight, no smem, full occupancy, DRAM-bound):
//   blocks [0, CONVB)      : all_memory fp32 -> g_Ah fp16
//   blocks [CONVB, +256)   : Ur_w fp32 -> g_Wh fp16
// =============================================================================
#define CONVB 102400
#define CONV_GRID (CONVB + 256)

__global__ void __launch_bounds__(256)
convert_kernel(const float* __restrict__ A, const float* __restrict__ Ur)
{
    const int tid = threadIdx.x;
    const int bid = blockIdx.x;

    if (bid < CONVB) {
        size_t gid = (size_t)bid * 256 + tid;
        float4 u = reinterpret_cast<const float4*>(A)[2 * gid];
        float4 v = reinterpret_cast<const float4*>(A)[2 * gid + 1];
        __half2 h0 = __float22half2_rn(make_float2(u.x, u.y));
        __half2 h1 = __float22half2_rn(make_float2(u.z, u.w));
        __half2 h2 = __float22half2_rn(make_float2(v.x, v.y));
        __half2 h3 = __float22half2_rn(make_float2(v.z, v.w));
        uint4 o;
        o.x = reinterpret_cast<uint32_t&>(h0); o.y = reinterpret_cast<uint32_t&>(h1);
        o.z = reinterpret_cast<uint32_t&>(h2); o.w = reinterpret_cast<uint32_t&>(h3);
        reinterpret_cast<uint4*>(g_Ah)[gid] = o;
    } else {
        int i = (bid - CONVB) * 256 + tid;       // float4 units, 65536
        float4 v = reinterpret_cast<const float4*>(Ur)[i];
        __half2 h0 = __float22half2_rn(make_float2(v.x, v.y));
        __half2 h1 = __float22half2_rn(make_float2(v.z, v.w));
        reinterpret_cast<__half2*>(g_Wh)[2 * i + 0] = h0;
        reinterpret_cast<__half2*>(g_Wh)[2 * i + 1] = h1;
    }
}

// =============================================================================
// K1: l = last_memory @ Wr^T  (SIMT fp32, ~52us)
// =============================================================================
__global__ void __launch_bounds__(256)
gemm_l_kernel(const float* __restrict__ A, const float* __restrict__ W)
{
    const int tid = threadIdx.x;
    const int tx  = tid & 15;
    const int ty  = tid >> 4;
    const int m0  = blockIdx.x * 64;
    const int o0  = blockIdx.y * 128;

    __shared__ float As[64][33];
    __shared__ float Ws[128][33];

    float acc[4][8];
#pragma unroll
    for (int i = 0; i < 4; i++)
#pragma unroll
        for (int j = 0; j < 8; j++) acc[i][j] = 0.0f;

    for (int k0 = 0; k0 < HDIM; k0 += 32) {
#pragma unroll
        for (int t = 0; t < 2; t++) {
            int f = t * 256 + tid, r = f >> 3, c4 = (f & 7) << 2;
            float4 v = *reinterpret_cast<const float4*>(&A[(size_t)(m0 + r) * HDIM + k0 + c4]);
            As[r][c4] = v.x; As[r][c4 + 1] = v.y; As[r][c4 + 2] = v.z; As[r][c4 + 3] = v.w;
        }
#pragma unroll
        for (int t = 0; t < 4; t++) {
            int f = t * 256 + tid, r = f >> 3, c4 = (f & 7) << 2;
            float4 v = *reinterpret_cast<const float4*>(&W[(size_t)(o0 + r) * HDIM + k0 + c4]);
            Ws[r][c4] = v.x; Ws[r][c4 + 1] = v.y; Ws[r][c4 + 2] = v.z; Ws[r][c4 + 3] = v.w;
        }
        __syncthreads();
#pragma unroll
        for (int kk = 0; kk < 32; kk++) {
            float a[4], w[8];
#pragma unroll
            for (int i = 0; i < 4; i++) a[i] = As[ty * 4 + i][kk];
#pragma unroll
            for (int j = 0; j < 8; j++) w[j] = Ws[tx + 16 * j][kk];
#pragma unroll
            for (int i = 0; i < 4; i++)
#pragma unroll
                for (int j = 0; j < 8; j++) acc[i][j] += a[i] * w[j];
        }
        __syncthreads();
    }
#pragma unroll
    for (int i = 0; i < 4; i++) {
        int m = m0 + ty * 4 + i;
#pragma unroll
        for (int j = 0; j < 8; j++)
            g_l[(size_t)m * HDIM + o0 + tx + 16 * j] = acc[i][j];
    }
}

// =============================================================================
// K2: fp16 HMMA GEMM, pure cp.async producer, 3-stage pipeline.
// CTA 128(m) x 128(n); stage = 32KB; occ 2 CTAs/SM.
// B fragments loaded pairwise with ldmatrix.x4 (6 LDSM/ks instead of 8).
// =============================================================================
#define OFF_VRE  0
#define OFF_STG  1024
#define OFF_B    16384
#define STAGE_SZ 32768
#define SMEM_TOTAL (OFF_STG + 3 * STAGE_SZ)   // 99328

__global__ void __launch_bounds__(256, 2)
score_kernel(const float* __restrict__ vre)     // [512]
{
    extern __shared__ char smem[];
    const uint32_t sb  = smem_u32(smem);
    const int tid = threadIdx.x;
    const int wid = tid >> 5;
    const int lid = tid & 31;
    const int wm  = wid >> 2;     // 0..1
    const int wn  = wid & 3;      // 0..3
    const int o0  = blockIdx.x * 128;
    const int m0  = blockIdx.y * 128;

    float* svre = reinterpret_cast<float*>(smem + OFF_VRE);
    if (tid < 128) svre[tid] = vre[o0 + tid];

    // producer roles: 64B of A + 64B of B per thread per chunk
    const int ar = tid >> 1;
    const int ah = (tid & 1);
    const __half* Abase = g_Ah + (size_t)(m0 + ar) * HDIM + ah * 32;
    const __half* Bbase = g_Wh + (size_t)(o0 + ar) * HDIM + ah * 32;
    const uint32_t roff = (uint32_t)(ar * 128 + ah * 64);

    float acc[4][4][4];
#pragma unroll
    for (int i = 0; i < 4; i++)
#pragma unroll
        for (int j = 0; j < 4; j++)
#pragma unroll
            for (int q = 0; q < 4; q++) acc[i][j][q] = 0.0f;

    // ---- prologue: fill stages 0,1 ----
#pragma unroll
    for (int p = 0; p < 2; p++) {
        const uint32_t st = sb + OFF_STG + p * STAGE_SZ;
        const int k0 = p * 64;
#pragma unroll
        for (int q = 0; q < 4; q++) {
            uint32_t o = SWZ(roff + q * 16);
            CPASYNC16(st + o,         Abase + k0 + q * 8);
            CPASYNC16(st + OFF_B + o, Bbase + k0 + q * 8);
        }
        CPASYNC_COMMIT();
    }

    // B x4 address: lanes 0-7 -> (rows, k0), 8-15 -> (rows, k16),
    //               16-23 -> (rows+8, k0), 24-31 -> (rows+8, k16)
    const uint32_t b_row_lo = wn * 32 + ((lid >> 4) & 1) * 8 + (lid & 7);
    const uint32_t b_k_off  = ((lid >> 3) & 1) * 16;

#pragma unroll 1
    for (int c = 0; c < 8; ++c) {
        if (c < 7) { CPASYNC_WAITG(1); } else { CPASYNC_WAITG(0); }
        __syncthreads();

        // fill stage c+2 (overlaps with this chunk's MMAs)
        if (c + 2 < 8) {
            const uint32_t stn = sb + OFF_STG + ((c + 2) % 3) * STAGE_SZ;
            const int k1 = (c + 2) * 64;
#pragma unroll
            for (int q = 0; q < 4; q++) {
                uint32_t o = SWZ(roff + q * 16);
                CPASYNC16(stn + o,         Abase + k1 + q * 8);
                CPASYNC16(stn + OFF_B + o, Bbase + k1 + q * 8);
            }
            CPASYNC_COMMIT();
        }

        // ---- MMAs on stage c%3 ----
        const uint32_t st = sb + OFF_STG + (c % 3) * STAGE_SZ;
#pragma unroll
        for (int ks = 0; ks < 4; ks++) {
            // B: two x4 loads cover nf = 0..3 (pairs)
            uint32_t bf[4][2];
#pragma unroll
            for (int pr = 0; pr < 2; pr++) {
                uint32_t row = b_row_lo + pr * 16;
                uint32_t kb  = ks * 32 + b_k_off;
                uint32_t t4[4];
                LDSM_X4(t4, st + OFF_B + SWZ(row * 128 + kb));
                bf[pr * 2 + 0][0] = t4[0]; bf[pr * 2 + 0][1] = t4[1];
                bf[pr * 2 + 1][0] = t4[2]; bf[pr * 2 + 1][1] = t4[3];
            }
#pragma unroll
            for (int mf = 0; mf < 4; mf++) {
                uint32_t row = wm * 64 + mf * 16 + (lid & 15);
                uint32_t kb  = ks * 32 + (lid >> 4) * 16;
                uint32_t af[4];
                LDSM_X4(af, st + SWZ(row * 128 + kb));
#pragma unroll
                for (int nf = 0; nf < 4; nf++)
                    MMA_F16(acc[mf][nf], af, bf[nf]);
            }
        }
    }

    // ---- fused epilogue: tanh + vre dot, per-row reduce ----
    float* part = reinterpret_cast<float*>(smem + OFF_STG);   // aliases stage 0
    const int r0 = lid >> 2;
    const int cb = 2 * (lid & 3);
#pragma unroll
    for (int mf = 0; mf < 4; mf++) {
        int R0 = wm * 64 + mf * 16 + r0;
        int R1 = R0 + 8;
        const float* lA = g_l + (size_t)((m0 + R0) / SEQ) * HDIM + o0;
        const float* lB = g_l + (size_t)((m0 + R1) / SEQ) * HDIM + o0;
        float p0 = 0.0f, p1 = 0.0f;
#pragma unroll
        for (int nf = 0; nf < 4; nf++) {
            int cl = wn * 32 + nf * 8 + cb;
            p0 += fast_tanh(acc[mf][nf][0] + lA[cl])     * svre[cl];
            p0 += fast_tanh(acc[mf][nf][1] + lA[cl + 1]) * svre[cl + 1];
            p1 += fast_tanh(acc[mf][nf][2] + lB[cl])     * svre[cl];
            p1 += fast_tanh(acc[mf][nf][3] + lB[cl + 1]) * svre[cl + 1];
        }
        p0 += __shfl_xor_sync(0xffffffffu, p0, 1);
        p0 += __shfl_xor_sync(0xffffffffu, p0, 2);
        p1 += __shfl_xor_sync(0xffffffffu, p1, 1);
        p1 += __shfl_xor_sync(0xffffffffu, p1, 2);
        if ((lid & 3) == 0) {
            part[R0 * 4 + wn] = p0;
            part[R1 * 4 + wn] = p1;
        }
    }
    __syncthreads();
    if (tid < 128) {
        float s = part[tid * 4 + 0] + part[tid * 4 + 1]
                + part[tid * 4 + 2] + part[tid * 4 + 3];
        g_spart[blockIdx.x][m0 + tid] = s;
    }
}

// =============================================================================
// K3: per-batch softmax over S, context (from fp16 A), 2-class head
// =============================================================================
__device__ __forceinline__ float block_reduce_max(float v, float* red, int tid) {
    red[tid] = v; __syncthreads();
#pragma unroll
    for (int off = 128; off > 0; off >>= 1) {
        if (tid < off) red[tid] = fmaxf(red[tid], red[tid + off]);
        __syncthreads();
    }
    float r = red[0]; __syncthreads(); return r;
}
__device__ __forceinline__ float block_reduce_sum(float v, float* red, int tid) {
    red[tid] = v; __syncthreads();
#pragma unroll
    for (int off = 128; off > 0; off >>= 1) {
        if (tid < off) red[tid] = red[tid] + red[tid + off];
        __syncthreads();
    }
    float r = red[0]; __syncthreads(); return r;
}

__global__ void __launch_bounds__(256)
finish_kernel(const float* __restrict__ wre,
              float* __restrict__ out)
{
    const int b = blockIdx.x, tid = threadIdx.x;
    __shared__ float attn[SEQ];
    __shared__ float red[256];

    float sc = -INFINITY;
    if (tid < SEQ) {
        float s = 0.0f;
#pragma unroll
        for (int p = 0; p < NPLANES; p++) s += g_spart[p][(size_t)b * SEQ + tid];
        sc = s;
    }
    float mx = block_reduce_max(sc, red, tid);
    float e = (tid < SEQ) ? expf(sc - mx) : 0.0f;
    float denom = block_reduce_sum(e, red, tid);
    if (tid < SEQ) attn[tid] = e / denom;
    __syncthreads();

    const __half* am = g_Ah + (size_t)b * SEQ * HDIM;
    float c0 = 0.0f, c1 = 0.0f;
#pragma unroll 4
    for (int s = 0; s < SEQ; s++) {
        float w = attn[s];
        __half2 h = *reinterpret_cast<const __half2*>(am + (size_t)s * HDIM + 2 * tid);
        float2 f = __half22float2(h);
        c0 = fmaf(w, f.x, c0);
        c1 = fmaf(w, f.y, c1);
    }
    float p0 = c0 * wre[2 * tid]        + c1 * wre[2 * tid + 1];
    float p1 = c0 * wre[HDIM + 2 * tid] + c1 * wre[HDIM + 2 * tid + 1];
    float L0 = block_reduce_sum(p0, red, tid);
    float L1 = block_reduce_sum(p1, red, tid);
    if (tid == 0) {
        float m  = fmaxf(L0, L1);
        float e0 = expf(L0 - m), e1 = expf(L1 - m);
        float inv = 1.0f / (e0 + e1);
        out[(size_t)b * 2 + 0] = e0 * inv;
        out[(size_t)b * 2 + 1] = e1 * inv;
    }
}

// =============================================================================
// launch
// =============================================================================
extern "C" void kernel_launch(void* const* d_in, const int* in_sizes, int n_in,
                              void* d_out, int out_size)
{
    const float* all_memory  = (const float*)d_in[0];
    const float* last_memory = (const float*)d_in[1];
    const float* Ur_w        = (const float*)d_in[2];
    const float* Wr_w        = (const float*)d_in[3];
    const float* Vre_w       = (const float*)d_in[4];
    const float* Wre_w       = (const float*)d_in[5];
    float* out = (float*)d_out;

    cudaFuncSetAttribute(score_kernel,
                         cudaFuncAttributeMaxDynamicSharedMemorySize, SMEM_TOTAL);

    convert_kernel<<<CONV_GRID, 256>>>(all_memory, Ur_w);
    gemm_l_kernel<<<dim3(BATCH / 64, HDIM / 128), 256>>>(last_memory, Wr_w);
    score_kernel<<<dim3(NPLANES, MTOT / 128), 256, SMEM_TOTAL>>>(Vre_w);
    finish_kernel<<<BATCH, 256>>>(Wre_w, out);
}

// round 9
// speedup vs baseline: 1.3959x; 1.3959x over previous
#include <cuda_runtime.h>
#include <cuda_fp16.h>
#include <math.h>
#include <cstdint>

#define BATCH 2048
#define SEQ   200
#define HDIM  512
#define MTOT  (BATCH * SEQ)   // 409600
#define NPLANES 4             // 4 o-tiles of 128 cols

// ---------------- static device scratch (no allocation) ----------------
__device__ float  g_l[BATCH * HDIM];          // Wr(last_memory)  [B,512]
__device__ float  g_spart[NPLANES][MTOT];     // partial scores
__device__ __half g_Wh[HDIM * HDIM];          // Ur_w fp16
__device__ __half g_Ah[(size_t)MTOT * HDIM];  // all_memory fp16 (419 MB)

// ======================= helpers =======================
__device__ __forceinline__ uint32_t smem_u32(const void* p) {
    uint32_t a;
    asm("{ .reg .u64 t; cvta.to.shared.u64 t, %1; cvt.u32.u64 %0, t; }"
        : "=r"(a) : "l"(p));
    return a;
}
#define SWZ(off) ((off) ^ (((off) >> 3) & 0x70))

#define LDSM_X4(r, a) \
    asm volatile("ldmatrix.sync.aligned.m8n8.x4.shared.b16 {%0,%1,%2,%3}, [%4];" \
        : "=r"((r)[0]), "=r"((r)[1]), "=r"((r)[2]), "=r"((r)[3]) : "r"(a))
#define LDSM_X2(r, a) \
    asm volatile("ldmatrix.sync.aligned.m8n8.x2.shared.b16 {%0,%1}, [%2];" \
        : "=r"((r)[0]), "=r"((r)[1]) : "r"(a))
#define MMA_F16(d, a, b) \
    asm volatile("mma.sync.aligned.m16n8k16.row.col.f32.f16.f16.f32 " \
        "{%0,%1,%2,%3},{%4,%5,%6,%7},{%8,%9},{%0,%1,%2,%3};" \
        : "+f"((d)[0]), "+f"((d)[1]), "+f"((d)[2]), "+f"((d)[3]) \
        : "r"((a)[0]), "r"((a)[1]), "r"((a)[2]), "r"((a)[3]), \
          "r"((b)[0]), "r"((b)[1]))
#define CPASYNC16(dst, src) \
    asm volatile("cp.async.cg.shared.global [%0], [%1], 16;" \
        :: "r"(dst), "l"(src) : "memory")
#define CPASYNC_COMMIT() asm volatile("cp.async.commit_group;" ::: "memory")
#define CPASYNC_WAITG(n) asm volatile("cp.async.wait_group %0;" :: "n"(n) : "memory")

__device__ __forceinline__ float fast_tanh(float x) {
    float e = __expf(2.0f * x);
    return 1.0f - __fdividef(2.0f, e + 1.0f);
}

// =============================================================================
// convert kernel (lightweight, no smem, full occupancy, DRAM-bound ~180us):
//   blocks [0, CONVB)      : all_memory fp32 -> g_Ah fp16
//   blocks [CONVB, +256)   : Ur_w fp32 -> g_Wh fp16
// =============================================================================
#define CONVB 102400
#define CONV_GRID (CONVB + 256)

__global__ void __launch_bounds__(256)
convert_kernel(const float* __restrict__ A, const float* __restrict__ Ur)
{
    const int tid = threadIdx.x;
    const int bid = blockIdx.x;

    if (bid < CONVB) {
        size_t gid = (size_t)bid * 256 + tid;
        float4 u = reinterpret_cast<const float4*>(A)[2 * gid];
        float4 v = reinterpret_cast<const float4*>(A)[2 * gid + 1];
        __half2 h0 = __float22half2_rn(make_float2(u.x, u.y));
        __half2 h1 = __float22half2_rn(make_float2(u.z, u.w));
        __half2 h2 = __float22half2_rn(make_float2(v.x, v.y));
        __half2 h3 = __float22half2_rn(make_float2(v.z, v.w));
        uint4 o;
        o.x = reinterpret_cast<uint32_t&>(h0); o.y = reinterpret_cast<uint32_t&>(h1);
        o.z = reinterpret_cast<uint32_t&>(h2); o.w = reinterpret_cast<uint32_t&>(h3);
        reinterpret_cast<uint4*>(g_Ah)[gid] = o;
    } else {
        int i = (bid - CONVB) * 256 + tid;       // float4 units, 65536
        float4 v = reinterpret_cast<const float4*>(Ur)[i];
        __half2 h0 = __float22half2_rn(make_float2(v.x, v.y));
        __half2 h1 = __float22half2_rn(make_float2(v.z, v.w));
        reinterpret_cast<__half2*>(g_Wh)[2 * i + 0] = h0;
        reinterpret_cast<__half2*>(g_Wh)[2 * i + 1] = h1;
    }
}

// =============================================================================
// K1: l = last_memory @ Wr^T  (SIMT fp32, ~52us)
// =============================================================================
__global__ void __launch_bounds__(256)
gemm_l_kernel(const float* __restrict__ A, const float* __restrict__ W)
{
    const int tid = threadIdx.x;
    const int tx  = tid & 15;
    const int ty  = tid >> 4;
    const int m0  = blockIdx.x * 64;
    const int o0  = blockIdx.y * 128;

    __shared__ float As[64][33];
    __shared__ float Ws[128][33];

    float acc[4][8];
#pragma unroll
    for (int i = 0; i < 4; i++)
#pragma unroll
        for (int j = 0; j < 8; j++) acc[i][j] = 0.0f;

    for (int k0 = 0; k0 < HDIM; k0 += 32) {
#pragma unroll
        for (int t = 0; t < 2; t++) {
            int f = t * 256 + tid, r = f >> 3, c4 = (f & 7) << 2;
            float4 v = *reinterpret_cast<const float4*>(&A[(size_t)(m0 + r) * HDIM + k0 + c4]);
            As[r][c4] = v.x; As[r][c4 + 1] = v.y; As[r][c4 + 2] = v.z; As[r][c4 + 3] = v.w;
        }
#pragma unroll
        for (int t = 0; t < 4; t++) {
            int f = t * 256 + tid, r = f >> 3, c4 = (f & 7) << 2;
            float4 v = *reinterpret_cast<const float4*>(&W[(size_t)(o0 + r) * HDIM + k0 + c4]);
            Ws[r][c4] = v.x; Ws[r][c4 + 1] = v.y; Ws[r][c4 + 2] = v.z; Ws[r][c4 + 3] = v.w;
        }
        __syncthreads();
#pragma unroll
        for (int kk = 0; kk < 32; kk++) {
            float a[4], w[8];
#pragma unroll
            for (int i = 0; i < 4; i++) a[i] = As[ty * 4 + i][kk];
#pragma unroll
            for (int j = 0; j < 8; j++) w[j] = Ws[tx + 16 * j][kk];
#pragma unroll
            for (int i = 0; i < 4; i++)
#pragma unroll
                for (int j = 0; j < 8; j++) acc[i][j] += a[i] * w[j];
        }
        __syncthreads();
    }
#pragma unroll
    for (int i = 0; i < 4; i++) {
        int m = m0 + ty * 4 + i;
#pragma unroll
        for (int j = 0; j < 8; j++)
            g_l[(size_t)m * HDIM + o0 + tx + 16 * j] = acc[i][j];
    }
}

// =============================================================================
// K2: fp16 HMMA GEMM, pure cp.async producer, 3-stage pipeline.
// (Round-7 proven version: X2 B loads — X4 pairing caused reg spills.)
// CTA 128(m) x 128(n); stage = 32KB; occ 2 CTAs/SM.
// =============================================================================
#define OFF_VRE  0
#define OFF_STG  1024
#define OFF_B    16384
#define STAGE_SZ 32768
#define SMEM_TOTAL (OFF_STG + 3 * STAGE_SZ)   // 99328

__global__ void __launch_bounds__(256, 2)
score_kernel(const float* __restrict__ vre)     // [512]
{
    extern __shared__ char smem[];
    const uint32_t sb  = smem_u32(smem);
    const int tid = threadIdx.x;
    const int wid = tid >> 5;
    const int lid = tid & 31;
    const int wm  = wid >> 2;     // 0..1
    const int wn  = wid & 3;      // 0..3
    const int o0  = blockIdx.x * 128;
    const int m0  = blockIdx.y * 128;

    float* svre = reinterpret_cast<float*>(smem + OFF_VRE);
    if (tid < 128) svre[tid] = vre[o0 + tid];

    // producer roles: 64B of A + 64B of B per thread per chunk (cp.async only)
    const int ar = tid >> 1;
    const int ah = (tid & 1);
    const __half* Abase = g_Ah + (size_t)(m0 + ar) * HDIM + ah * 32;
    const __half* Bbase = g_Wh + (size_t)(o0 + ar) * HDIM + ah * 32;
    const uint32_t roff = (uint32_t)(ar * 128 + ah * 64);

    float acc[4][4][4];
#pragma unroll
    for (int i = 0; i < 4; i++)
#pragma unroll
        for (int j = 0; j < 4; j++)
#pragma unroll
            for (int q = 0; q < 4; q++) acc[i][j][q] = 0.0f;

    // ---- prologue: fill stages 0,1 (chunks 0,1) ----
#pragma unroll
    for (int p = 0; p < 2; p++) {
        const uint32_t st = sb + OFF_STG + p * STAGE_SZ;
        const int k0 = p * 64;
#pragma unroll
        for (int q = 0; q < 4; q++) {
            uint32_t o = SWZ(roff + q * 16);
            CPASYNC16(st + o,         Abase + k0 + q * 8);
            CPASYNC16(st + OFF_B + o, Bbase + k0 + q * 8);
        }
        CPASYNC_COMMIT();
    }

#pragma unroll 1
    for (int c = 0; c < 8; ++c) {
        if (c < 7) { CPASYNC_WAITG(1); } else { CPASYNC_WAITG(0); }
        __syncthreads();

        // fill stage c+2 (overlaps with this chunk's MMAs)
        if (c + 2 < 8) {
            const uint32_t stn = sb + OFF_STG + ((c + 2) % 3) * STAGE_SZ;
            const int k1 = (c + 2) * 64;
#pragma unroll
            for (int q = 0; q < 4; q++) {
                uint32_t o = SWZ(roff + q * 16);
                CPASYNC16(stn + o,         Abase + k1 + q * 8);
                CPASYNC16(stn + OFF_B + o, Bbase + k1 + q * 8);
            }
            CPASYNC_COMMIT();
        }

        // ---- MMAs on stage c%3 ----
        const uint32_t st = sb + OFF_STG + (c % 3) * STAGE_SZ;
#pragma unroll
        for (int ks = 0; ks < 4; ks++) {
            uint32_t bf[4][2];
#pragma unroll
            for (int nf = 0; nf < 4; nf++) {
                uint32_t row = wn * 32 + nf * 8 + (lid & 7);
                uint32_t kb  = ks * 32 + ((lid >> 3) & 1) * 16;
                LDSM_X2(bf[nf], st + OFF_B + SWZ(row * 128 + kb));
            }
#pragma unroll
            for (int mf = 0; mf < 4; mf++) {
                uint32_t row = wm * 64 + mf * 16 + (lid & 15);
                uint32_t kb  = ks * 32 + (lid >> 4) * 16;
                uint32_t af[4];
                LDSM_X4(af, st + SWZ(row * 128 + kb));
#pragma unroll
                for (int nf = 0; nf < 4; nf++)
                    MMA_F16(acc[mf][nf], af, bf[nf]);
            }
        }
    }

    // ---- fused epilogue: tanh + vre dot, per-row reduce ----
    float* part = reinterpret_cast<float*>(smem + OFF_STG);   // aliases stage 0
    const int r0 = lid >> 2;
    const int cb = 2 * (lid & 3);
#pragma unroll
    for (int mf = 0; mf < 4; mf++) {
        int R0 = wm * 64 + mf * 16 + r0;
        int R1 = R0 + 8;
        const float* lA = g_l + (size_t)((m0 + R0) / SEQ) * HDIM + o0;
        const float* lB = g_l + (size_t)((m0 + R1) / SEQ) * HDIM + o0;
        float p0 = 0.0f, p1 = 0.0f;
#pragma unroll
        for (int nf = 0; nf < 4; nf++) {
            int cl = wn * 32 + nf * 8 + cb;
            p0 += fast_tanh(acc[mf][nf][0] + lA[cl])     * svre[cl];
            p0 += fast_tanh(acc[mf][nf][1] + lA[cl + 1]) * svre[cl + 1];
            p1 += fast_tanh(acc[mf][nf][2] + lB[cl])     * svre[cl];
            p1 += fast_tanh(acc[mf][nf][3] + lB[cl + 1]) * svre[cl + 1];
        }
        p0 += __shfl_xor_sync(0xffffffffu, p0, 1);
        p0 += __shfl_xor_sync(0xffffffffu, p0, 2);
        p1 += __shfl_xor_sync(0xffffffffu, p1, 1);
        p1 += __shfl_xor_sync(0xffffffffu, p1, 2);
        if ((lid & 3) == 0) {
            part[R0 * 4 + wn] = p0;
            part[R1 * 4 + wn] = p1;
        }
    }
    __syncthreads();
    if (tid < 128) {
        float s = part[tid * 4 + 0] + part[tid * 4 + 1]
                + part[tid * 4 + 2] + part[tid * 4 + 3];
        g_spart[blockIdx.x][m0 + tid] = s;
    }
}

// =============================================================================
// K3: per-batch softmax over S, context (from fp16 A), 2-class head
// =============================================================================
__device__ __forceinline__ float block_reduce_max(float v, float* red, int tid) {
    red[tid] = v; __syncthreads();
#pragma unroll
    for (int off = 128; off > 0; off >>= 1) {
        if (tid < off) red[tid] = fmaxf(red[tid], red[tid + off]);
        __syncthreads();
    }
    float r = red[0]; __syncthreads(); return r;
}
__device__ __forceinline__ float block_reduce_sum(float v, float* red, int tid) {
    red[tid] = v; __syncthreads();
#pragma unroll
    for (int off = 128; off > 0; off >>= 1) {
        if (tid < off) red[tid] = red[tid] + red[tid + off];
        __syncthreads();
    }
    float r = red[0]; __syncthreads(); return r;
}

__global__ void __launch_bounds__(256)
finish_kernel(const float* __restrict__ wre,
              float* __restrict__ out)
{
    const int b = blockIdx.x, tid = threadIdx.x;
    __shared__ float attn[SEQ];
    __shared__ float red[256];

    float sc = -INFINITY;
    if (tid < SEQ) {
        float s = 0.0f;
#pragma unroll
        for (int p = 0; p < NPLANES; p++) s += g_spart[p][(size_t)b * SEQ + tid];
        sc = s;
    }
    float mx = block_reduce_max(sc, red, tid);
    float e = (tid < SEQ) ? expf(sc - mx) : 0.0f;
    float denom = block_reduce_sum(e, red, tid);
    if (tid < SEQ) attn[tid] = e / denom;
    __syncthreads();

    // ctx from fp16 A: two independent accumulator pairs (even/odd s) for MLP
    const __half* am = g_Ah + (size_t)b * SEQ * HDIM;
    float c0a = 0.0f, c1a = 0.0f, c0b = 0.0f, c1b = 0.0f;
#pragma unroll 2
    for (int s = 0; s < SEQ; s += 2) {
        float w0 = attn[s];
        float w1 = attn[s + 1];
        __half2 ha = *reinterpret_cast<const __half2*>(am + (size_t)s * HDIM + 2 * tid);
        __half2 hb = *reinterpret_cast<const __half2*>(am + (size_t)(s + 1) * HDIM + 2 * tid);
        float2 fa = __half22float2(ha);
        float2 fb = __half22float2(hb);
        c0a = fmaf(w0, fa.x, c0a);
        c1a = fmaf(w0, fa.y, c1a);
        c0b = fmaf(w1, fb.x, c0b);
        c1b = fmaf(w1, fb.y, c1b);
    }
    float c0 = c0a + c0b, c1 = c1a + c1b;
    float p0 = c0 * wre[2 * tid]        + c1 * wre[2 * tid + 1];
    float p1 = c0 * wre[HDIM + 2 * tid] + c1 * wre[HDIM + 2 * tid + 1];
    float L0 = block_reduce_sum(p0, red, tid);
    float L1 = block_reduce_sum(p1, red, tid);
    if (tid == 0) {
        float m  = fmaxf(L0, L1);
        float e0 = expf(L0 - m), e1 = expf(L1 - m);
        float inv = 1.0f / (e0 + e1);
        out[(size_t)b * 2 + 0] = e0 * inv;
        out[(size_t)b * 2 + 1] = e1 * inv;
    }
}

// =============================================================================
// launch
// =============================================================================
extern "C" void kernel_launch(void* const* d_in, const int* in_sizes, int n_in,
                              void* d_out, int out_size)
{
    const float* all_memory  = (const float*)d_in[0];
    const float* last_memory = (const float*)d_in[1];
    const float* Ur_w        = (const float*)d_in[2];
    const float* Wr_w        = (const float*)d_in[3];
    const float* Vre_w       = (const float*)d_in[4];
    const float* Wre_w       = (const float*)d_in[5];
    float* out = (float*)d_out;

    cudaFuncSetAttribute(score_kernel,
                         cudaFuncAttributeMaxDynamicSharedMemorySize, SMEM_TOTAL);

    convert_kernel<<<CONV_GRID, 256>>>(all_memory, Ur_w);
    gemm_l_kernel<<<dim3(BATCH / 64, HDIM / 128), 256>>>(last_memory, Wr_w);
    score_kernel<<<dim3(NPLANES, MTOT / 128), 256, SMEM_TOTAL>>>(Vre_w);
    finish_kernel<<<BATCH, 256>>>(Wre_w, out);
}